// round 14
// baseline (speedup 1.0000x reference)
#include <cuda_runtime.h>
#include <cuda_fp16.h>
#include <math.h>
#include <stdint.h>

#define DIMX   1024
#define HEADS  16
#define HD     64
#define WIN    5
#define SEQ    2048
#define MTOK   4096
#define EPSLN  1e-5f

// ===========================================================================
// PTX helpers (baseline compute_103-safe: cp.async / ldmatrix / mma.sync)
// ===========================================================================
__device__ __forceinline__ uint32_t smem_to_u32(const void* p) {
    uint32_t a;
    asm("{ .reg .u64 t; cvta.to.shared.u64 t, %1; cvt.u32.u64 %0, t; }" : "=r"(a) : "l"(p));
    return a;
}
__device__ __forceinline__ void cp16(uint32_t dst, const void* src) {
    asm volatile("cp.async.cg.shared.global [%0], [%1], 16;" :: "r"(dst), "l"(src) : "memory");
}
#define CP_COMMIT() asm volatile("cp.async.commit_group;" ::: "memory")
#define CP_WAIT0()  asm volatile("cp.async.wait_group 0;"  ::: "memory")
#define CP_WAIT1()  asm volatile("cp.async.wait_group 1;"  ::: "memory")

__device__ __forceinline__ void ldsm4(uint32_t* r, uint32_t addr) {
    asm volatile("ldmatrix.sync.aligned.m8n8.x4.shared.b16 {%0,%1,%2,%3}, [%4];"
        : "=r"(r[0]), "=r"(r[1]), "=r"(r[2]), "=r"(r[3]) : "r"(addr));
}
// fp16-accumulate MMA: D(f16x2 pair) = A*B + C, chained in-register
__device__ __forceinline__ void mma16816h(uint32_t& c01, uint32_t& c23,
                                          const uint32_t* a, uint32_t b0, uint32_t b1) {
    asm volatile("mma.sync.aligned.m16n8k16.row.col.f16.f16.f16.f16 "
        "{%0,%1}, {%2,%3,%4,%5}, {%6,%7}, {%0,%1};"
        : "+r"(c01), "+r"(c23)
        : "r"(a[0]), "r"(a[1]), "r"(a[2]), "r"(a[3]), "r"(b0), "r"(b1));
}

// ===========================================================================
// Scratch: all GEMM operands plain fp16 [rows, K]
// ===========================================================================
__device__ __align__(256) float g_qkv    [MTOK * 3 * DIMX];
__device__ __align__(256) float g_attnout[MTOK * DIMX];
__device__ __align__(256) float g_x1     [MTOK * DIMX];
__device__ __align__(256) float g_mlp    [MTOK * DIMX];

__device__ __align__(256) __half g_xs   [MTOK * DIMX];
__device__ __align__(256) __half g_attns[MTOK * DIMX];
__device__ __align__(256) __half g_x1s  [MTOK * DIMX];
__device__ __align__(256) __half g_hs   [MTOK * 4096];
__device__ __align__(256) __half g_wins [3072 * 1024];
__device__ __align__(256) __half g_wouts[1024 * 1024];
__device__ __align__(256) __half g_w1s  [4096 * 1024];
__device__ __align__(256) __half g_w2s  [1024 * 4096];

__device__ __forceinline__ float gelu_exact(float x) {
    return 0.5f * x * (1.0f + erff(x * 0.70710678118654752440f));
}

// ===========================================================================
// One fused fp32->fp16 cast over all 5 tensors (grid-stride, float4 units)
// ===========================================================================
#define CAST_UNITS 4194304   // 16777216 elements / 4

__global__ __launch_bounds__(256)
void cast_all_kernel(const float* __restrict__ x,   const float* __restrict__ w_in,
                     const float* __restrict__ wo,  const float* __restrict__ w1,
                     const float* __restrict__ w2,
                     __half* __restrict__ xs,   __half* __restrict__ wins,
                     __half* __restrict__ wouts, __half* __restrict__ w1s,
                     __half* __restrict__ w2s)
{
    const unsigned stride = gridDim.x * 256u;
    for (unsigned u = blockIdx.x * 256u + threadIdx.x; u < CAST_UNITS; u += stride) {
        size_t e = (size_t)u * 4;
        const float* in; __half* out; size_t off;
        if      (e <  4194304) { in = x;    out = xs;    off = e; }
        else if (e <  7340032) { in = w_in; out = wins;  off = e - 4194304; }
        else if (e <  8388608) { in = wo;   out = wouts; off = e - 7340032; }
        else if (e < 12582912) { in = w1;   out = w1s;   off = e - 8388608; }
        else                   { in = w2;   out = w2s;   off = e - 12582912; }
        float4 v = *(const float4*)(in + off);
        *(__half2*)(out + off)     = __half2{__float2half_rn(v.x), __float2half_rn(v.y)};
        *(__half2*)(out + off + 2) = __half2{__float2half_rn(v.z), __float2half_rn(v.w)};
    }
}

// ===========================================================================
// HMMA GEMM: C = A x W^T (+bias), fp16 operands.
// f16-accumulate within each K=64 chunk (4 chained MMAs), promoted to fp32
// once per chunk per fragment (tests/exploits full-rate f16-acc HMMA).
// Tile 128x128, 128 threads (4 warps, 2x2), warp tile 64x64, 2 CTAs/SM.
// 3-stage cp.async pipeline; smem 3 x 32K = 96K per CTA.
// OUT_MODE 0: fp32 C + bias.  OUT_MODE 1: gelu(C+bias) -> fp16.
// ===========================================================================
#define STAGE_B 32768
#define GEMM_SMEM (3 * STAGE_B)

__device__ __forceinline__ void load_ab(const __half* A, const __half* W,
                                        int K, uint32_t sb, int tid,
                                        int m0, int n0, int c, int s)
{
    const size_t rb = (size_t)2 * K;                 // row bytes (K halves)
    const char* Ab = (const char*)A + (size_t)m0 * rb + (size_t)c * 128;
    const char* Wb = (const char*)W + (size_t)n0 * rb + (size_t)c * 128;
    const uint32_t as = sb + s * STAGE_B;
    const uint32_t ws = as + 16384;
#pragma unroll
    for (int i = 0; i < 8; i++) {                    // A: 128 rows x 128B
        int id = tid + i * 128;
        int r = id >> 3, cb = (id & 7) * 16;
        uint32_t off = (uint32_t)(r * 128 + cb); off ^= (off >> 3) & 0x70;
        cp16(as + off, Ab + (size_t)r * rb + cb);
    }
#pragma unroll
    for (int i = 0; i < 8; i++) {                    // W: 128 rows x 128B
        int id = tid + i * 128;
        int r = id >> 3, cb = (id & 7) * 16;
        uint32_t off = (uint32_t)(r * 128 + cb); off ^= (off >> 3) & 0x70;
        cp16(ws + off, Wb + (size_t)r * rb + cb);
    }
    CP_COMMIT();
}

template <int OUT_MODE>
__global__ __launch_bounds__(128, 2)
void gemm_kernel(const __half* __restrict__ A, const __half* __restrict__ W,
                 const float* __restrict__ bias, float* __restrict__ outF,
                 __half* __restrict__ outS, int Ntot, int K)
{
    extern __shared__ char smem[];
    const uint32_t sb = smem_to_u32(smem);
    const int tid = threadIdx.x, wid = tid >> 5, lane = tid & 31;
    const int wm = wid >> 1, wn = wid & 1;           // 2 x 2 warps
    const int m0 = blockIdx.y * 128, n0 = blockIdx.x * 128;
    const int NC = K / 64;

    float acc[4][8][4];                              // warp tile 64x64
#pragma unroll
    for (int i = 0; i < 4; i++)
#pragma unroll
        for (int j = 0; j < 8; j++)
#pragma unroll
            for (int q = 0; q < 4; q++) acc[i][j][q] = 0.0f;

    // A ldsm4 addressing
    const int aq   = lane >> 3;
    const int ari  = lane & 7;
    const int arow = wm * 64 + (aq & 1) * 8 + ari;   // + ma*16
    const int akc  = aq >> 1;
    // B ldsm4 addressing (pair of n-atoms per ldsm4)
    const int bna2 = lane >> 4;
    const int bq   = (lane >> 3) & 1;
    const int bri  = lane & 7;
    const int brow = wn * 64 + bna2 * 8 + bri;       // + pair*16

    load_ab(A, W, K, sb, tid, m0, n0, 0, 0);
    load_ab(A, W, K, sb, tid, m0, n0, 1, 1);

    for (int c = 0; c < NC; c++) {
        if (c + 1 == NC) { CP_WAIT0(); } else { CP_WAIT1(); }
        __syncthreads();
        if (c + 2 < NC) load_ab(A, W, K, sb, tid, m0, n0, c + 2, (c + 2) % 3);

        const int s = c % 3;
        const uint32_t as = sb + s * STAGE_B;
        const uint32_t ws = as + 16384;

        // Process n-range in two halves (na 0-3, then 4-7):
        // B frags for this half x all 4 k-steps resident (32 regs).
#pragma unroll
        for (int hv = 0; hv < 2; hv++) {
            uint32_t bh[2][4][4];                    // [pp][ks][4]
#pragma unroll
            for (int ks = 0; ks < 4; ks++) {
                const int kc = ks * 2;
                const uint32_t bsw = ((uint32_t)((kc + bq) ^ bri)) << 4;
#pragma unroll
                for (int pp = 0; pp < 2; pp++) {
                    const int p = hv * 2 + pp;
                    ldsm4(bh[pp][ks], ws + (brow + p * 16) * 128 + bsw);
                }
            }
#pragma unroll
            for (int ma = 0; ma < 4; ma++) {
                uint32_t ah[4][4];                   // [ks][4]
#pragma unroll
                for (int ks = 0; ks < 4; ks++) {
                    const int kc = ks * 2;
                    const uint32_t asw = ((uint32_t)((kc + akc) ^ ari)) << 4;
                    ldsm4(ah[ks], as + (arow + ma * 16) * 128 + asw);
                }
#pragma unroll
                for (int l = 0; l < 4; l++) {
                    const int pp = l >> 1, j = (l & 1) * 2;
                    const int na = hv * 4 + l;
                    uint32_t c01 = 0, c23 = 0;       // f16 segment accumulator
#pragma unroll
                    for (int ks = 0; ks < 4; ks++)
                        mma16816h(c01, c23, ah[ks], bh[pp][ks][j], bh[pp][ks][j + 1]);
                    float2 f0 = __half22float2(*reinterpret_cast<__half2*>(&c01));
                    float2 f1 = __half22float2(*reinterpret_cast<__half2*>(&c23));
                    acc[ma][na][0] += f0.x; acc[ma][na][1] += f0.y;
                    acc[ma][na][2] += f1.x; acc[ma][na][3] += f1.y;
                }
            }
        }
    }

    // epilogue
    const int lrow = lane >> 2;
    const int lcol = (lane & 3) * 2;
#pragma unroll
    for (int ma = 0; ma < 4; ma++) {
        const int r0 = m0 + wm * 64 + ma * 16 + lrow;
#pragma unroll
        for (int na = 0; na < 8; na++) {
            const int c0 = n0 + wn * 64 + na * 8 + lcol;
            float v0 = acc[ma][na][0] + bias[c0];
            float v1 = acc[ma][na][1] + bias[c0 + 1];
            float v2 = acc[ma][na][2] + bias[c0];
            float v3 = acc[ma][na][3] + bias[c0 + 1];
            if (OUT_MODE == 0) {
                *(float2*)(outF + (size_t)r0 * Ntot + c0)     = make_float2(v0, v1);
                *(float2*)(outF + (size_t)(r0+8) * Ntot + c0) = make_float2(v2, v3);
            } else {
                v0 = gelu_exact(v0); v1 = gelu_exact(v1);
                v2 = gelu_exact(v2); v3 = gelu_exact(v3);
                *(__half2*)(outS + (size_t)r0 * Ntot + c0) =
                    __half2{__float2half_rn(v0), __float2half_rn(v1)};
                *(__half2*)(outS + (size_t)(r0+8) * Ntot + c0) =
                    __half2{__float2half_rn(v2), __float2half_rn(v3)};
            }
        }
    }
}

// ===========================================================================
// Local causal attention (fp32 in, fp16 out)
// ===========================================================================
__global__ __launch_bounds__(256)
void attn_kernel(const float* __restrict__ qkv, __half* __restrict__ attns)
{
    const int w    = (blockIdx.x * blockDim.x + threadIdx.x) >> 5;
    const int lane = threadIdx.x & 31;
    if (w >= MTOK * HEADS) return;
    const int m = w / HEADS, h = w - m * HEADS, s = m & (SEQ - 1);

    const float* qp = qkv + (size_t)m * (3 * DIMX) + h * HD;
    const float qa = qp[lane], qb = qp[lane + 32];
    const int jlo = (s >= WIN - 1) ? (s - (WIN - 1)) : 0;
    const int cnt = s - jlo + 1;
    const int mlo = m - (s - jlo);

    float sc[WIN];
#pragma unroll
    for (int t = 0; t < WIN; t++) {
        sc[t] = -3.0e38f;
        if (t < cnt) {
            const float* kp = qkv + (size_t)(mlo + t) * (3 * DIMX) + DIMX + h * HD;
            float d = qa * kp[lane] + qb * kp[lane + 32];
#pragma unroll
            for (int o = 16; o > 0; o >>= 1) d += __shfl_xor_sync(0xffffffffu, d, o);
            sc[t] = d * 0.125f;
        }
    }
    float mx = sc[0];
#pragma unroll
    for (int t = 1; t < WIN; t++) mx = fmaxf(mx, sc[t]);
    float p[WIN], sum = 0.0f;
#pragma unroll
    for (int t = 0; t < WIN; t++) { p[t] = (t < cnt) ? __expf(sc[t] - mx) : 0.0f; sum += p[t]; }
    const float inv = 1.0f / sum;

    float oa = 0.0f, ob = 0.0f;
#pragma unroll
    for (int t = 0; t < WIN; t++) {
        if (t < cnt) {
            const float* vp = qkv + (size_t)(mlo + t) * (3 * DIMX) + 2 * DIMX + h * HD;
            oa = fmaf(p[t], vp[lane], oa);
            ob = fmaf(p[t], vp[lane + 32], ob);
        }
    }
    const size_t base = (size_t)m * DIMX + h * HD;
    attns[base + lane]      = __float2half_rn(oa * inv);
    attns[base + lane + 32] = __float2half_rn(ob * inv);
}

// ===========================================================================
// Residual + LayerNorm, float4-vectorized (optionally emit fp16 cast)
// ===========================================================================
template <int CAST>
__global__ __launch_bounds__(256)
void ln_residual_kernel(const float* __restrict__ A, const float* __restrict__ Bv,
                        const float* __restrict__ g, const float* __restrict__ beta,
                        float* __restrict__ out, __half* __restrict__ outs)
{
    const int m = blockIdx.x, tid = threadIdx.x;
    const float4* a4 = (const float4*)(A  + (size_t)m * DIMX);
    const float4* b4 = (const float4*)(Bv + (size_t)m * DIMX);

    float4 av = a4[tid], bv = b4[tid];
    float4 v = make_float4(av.x + bv.x, av.y + bv.y, av.z + bv.z, av.w + bv.w);
    float s  = v.x + v.y + v.z + v.w;
    float s2 = v.x*v.x + v.y*v.y + v.z*v.z + v.w*v.w;
#pragma unroll
    for (int o = 16; o > 0; o >>= 1) {
        s  += __shfl_xor_sync(0xffffffffu, s,  o);
        s2 += __shfl_xor_sync(0xffffffffu, s2, o);
    }
    __shared__ float shs[8], shs2[8], shm, shr;
    const int wid = tid >> 5, lane = tid & 31;
    if (lane == 0) { shs[wid] = s; shs2[wid] = s2; }
    __syncthreads();
    if (tid == 0) {
        float S = 0.0f, S2 = 0.0f;
#pragma unroll
        for (int i = 0; i < 8; i++) { S += shs[i]; S2 += shs2[i]; }
        float mean = S * (1.0f / DIMX);
        shm = mean;
        shr = rsqrtf(S2 * (1.0f / DIMX) - mean * mean + EPSLN);
    }
    __syncthreads();
    const float mean = shm, rstd = shr;
    float4 gv = ((const float4*)g)[tid];
    float4 be = ((const float4*)beta)[tid];
    float4 y;
    y.x = (v.x - mean) * rstd * gv.x + be.x;
    y.y = (v.y - mean) * rstd * gv.y + be.y;
    y.z = (v.z - mean) * rstd * gv.z + be.z;
    y.w = (v.w - mean) * rstd * gv.w + be.w;
    ((float4*)(out + (size_t)m * DIMX))[tid] = y;
    if (CAST) {
        __half2* o2 = (__half2*)(outs + (size_t)m * DIMX + tid * 4);
        o2[0] = __half2{__float2half_rn(y.x), __float2half_rn(y.y)};
        o2[1] = __half2{__float2half_rn(y.z), __float2half_rn(y.w)};
    }
}

// ===========================================================================
// kernel_launch
// ===========================================================================
extern "C" void kernel_launch(void* const* d_in, const int* in_sizes, int n_in,
                              void* d_out, int out_size)
{
    const float* x     = (const float*)d_in[0];
    const float* w_in  = (const float*)d_in[1];
    const float* b_in  = (const float*)d_in[2];
    const float* w_out = (const float*)d_in[3];
    const float* b_out = (const float*)d_in[4];
    const float* ln1_g = (const float*)d_in[5];
    const float* ln1_b = (const float*)d_in[6];
    const float* ln2_g = (const float*)d_in[7];
    const float* ln2_b = (const float*)d_in[8];
    const float* w1    = (const float*)d_in[9];
    const float* b1    = (const float*)d_in[10];
    const float* w2    = (const float*)d_in[11];
    const float* b2    = (const float*)d_in[12];
    float* out = (float*)d_out;

    float *qkv, *attnout, *x1, *mlp;
    __half *xs, *attns, *x1s, *hs, *wins, *wouts, *w1s, *w2s;
    cudaGetSymbolAddress((void**)&qkv,     g_qkv);
    cudaGetSymbolAddress((void**)&attnout, g_attnout);
    cudaGetSymbolAddress((void**)&x1,      g_x1);
    cudaGetSymbolAddress((void**)&mlp,     g_mlp);
    cudaGetSymbolAddress((void**)&xs,      g_xs);
    cudaGetSymbolAddress((void**)&attns,   g_attns);
    cudaGetSymbolAddress((void**)&x1s,     g_x1s);
    cudaGetSymbolAddress((void**)&hs,      g_hs);
    cudaGetSymbolAddress((void**)&wins,    g_wins);
    cudaGetSymbolAddress((void**)&wouts,   g_wouts);
    cudaGetSymbolAddress((void**)&w1s,     g_w1s);
    cudaGetSymbolAddress((void**)&w2s,     g_w2s);

    cudaFuncSetAttribute(gemm_kernel<0>, cudaFuncAttributeMaxDynamicSharedMemorySize, GEMM_SMEM);
    cudaFuncSetAttribute(gemm_kernel<1>, cudaFuncAttributeMaxDynamicSharedMemorySize, GEMM_SMEM);

    // 0. all fp32 -> fp16 casts in one launch
    cast_all_kernel<<<8192, 256>>>(x, w_in, w_out, w1, w2, xs, wins, wouts, w1s, w2s);

    // 1. qkv = x @ w_in^T + b_in           [4096, 3072], K=1024
    gemm_kernel<0><<<dim3(24, 32), 128, GEMM_SMEM>>>(xs, wins, b_in, qkv, nullptr, 3072, 1024);
    // 2. attention -> fp16
    attn_kernel<<<(MTOK * HEADS * 32) / 256, 256>>>(qkv, attns);
    // 3. attnout = attn @ w_out^T + b_out  [4096, 1024], K=1024
    gemm_kernel<0><<<dim3(8, 32), 128, GEMM_SMEM>>>(attns, wouts, b_out, attnout, nullptr, 1024, 1024);
    // 4. x1 = LN1(x + attnout), + fp16 cast
    ln_residual_kernel<1><<<MTOK, 256>>>(x, attnout, ln1_g, ln1_b, x1, x1s);
    // 5. h = gelu(x1 @ w1^T + b1) -> fp16  [4096, 4096], K=1024
    gemm_kernel<1><<<dim3(32, 32), 128, GEMM_SMEM>>>(x1s, w1s, b1, nullptr, hs, 4096, 1024);
    // 6. mlp = h @ w2^T + b2               [4096, 1024], K=4096
    gemm_kernel<0><<<dim3(8, 32), 128, GEMM_SMEM>>>(hs, w2s, b2, mlp, nullptr, 1024, 4096);
    // 7. out = LN2(x1 + mlp)
    ln_residual_kernel<0><<<MTOK, 256>>>(x1, mlp, ln2_g, ln2_b, out, nullptr);

    (void)in_sizes; (void)n_in; (void)out_size;
}

// round 15
// speedup vs baseline: 1.2810x; 1.2810x over previous
#include <cuda_runtime.h>
#include <cuda_fp16.h>
#include <math.h>
#include <stdint.h>

#define DIMX   1024
#define HEADS  16
#define HD     64
#define WIN    5
#define SEQ    2048
#define MTOK   4096
#define EPSLN  1e-5f

// ===========================================================================
// PTX helpers (baseline compute_103-safe: cp.async / ldmatrix / mma.sync)
// ===========================================================================
__device__ __forceinline__ uint32_t smem_to_u32(const void* p) {
    uint32_t a;
    asm("{ .reg .u64 t; cvta.to.shared.u64 t, %1; cvt.u32.u64 %0, t; }" : "=r"(a) : "l"(p));
    return a;
}
__device__ __forceinline__ void cp16(uint32_t dst, const void* src) {
    asm volatile("cp.async.cg.shared.global [%0], [%1], 16;" :: "r"(dst), "l"(src) : "memory");
}
#define CP_COMMIT() asm volatile("cp.async.commit_group;" ::: "memory")
#define CP_WAIT0()  asm volatile("cp.async.wait_group 0;"  ::: "memory")
#define CP_WAIT1()  asm volatile("cp.async.wait_group 1;"  ::: "memory")

__device__ __forceinline__ void ldsm4(uint32_t* r, uint32_t addr) {
    asm volatile("ldmatrix.sync.aligned.m8n8.x4.shared.b16 {%0,%1,%2,%3}, [%4];"
        : "=r"(r[0]), "=r"(r[1]), "=r"(r[2]), "=r"(r[3]) : "r"(addr));
}
__device__ __forceinline__ void mma16816(float* d, const uint32_t* a, const uint32_t* b) {
    asm volatile("mma.sync.aligned.m16n8k16.row.col.f32.f16.f16.f32 "
        "{%0,%1,%2,%3}, {%4,%5,%6,%7}, {%8,%9}, {%0,%1,%2,%3};"
        : "+f"(d[0]), "+f"(d[1]), "+f"(d[2]), "+f"(d[3])
        : "r"(a[0]), "r"(a[1]), "r"(a[2]), "r"(a[3]), "r"(b[0]), "r"(b[1]));
}

// ===========================================================================
// Scratch: all GEMM operands plain fp16 [rows, K]
// ===========================================================================
__device__ __align__(256) float g_qkv    [MTOK * 3 * DIMX];
__device__ __align__(256) float g_attnout[MTOK * DIMX];
__device__ __align__(256) float g_x1     [MTOK * DIMX];
__device__ __align__(256) float g_mlp    [MTOK * DIMX];

__device__ __align__(256) __half g_xs   [MTOK * DIMX];
__device__ __align__(256) __half g_attns[MTOK * DIMX];
__device__ __align__(256) __half g_x1s  [MTOK * DIMX];
__device__ __align__(256) __half g_hs   [MTOK * 4096];
__device__ __align__(256) __half g_wins [3072 * 1024];
__device__ __align__(256) __half g_wouts[1024 * 1024];
__device__ __align__(256) __half g_w1s  [4096 * 1024];
__device__ __align__(256) __half g_w2s  [1024 * 4096];

__device__ __forceinline__ float gelu_exact(float x) {
    return 0.5f * x * (1.0f + erff(x * 0.70710678118654752440f));
}

// ===========================================================================
// Branchless fused fp32->fp16 cast: one float4 unit per thread, the source
// region resolved ONCE per block (all boundaries are multiples of 256 units).
// Unit boundaries: x 1048576 | w_in 1835008 | w_out 2097152 | w1 3145728 | w2 4194304
// ===========================================================================
__global__ __launch_bounds__(256)
void cast_all_kernel(const float* __restrict__ x,   const float* __restrict__ w_in,
                     const float* __restrict__ wo,  const float* __restrict__ w1,
                     const float* __restrict__ w2,
                     __half* __restrict__ xs,   __half* __restrict__ wins,
                     __half* __restrict__ wouts, __half* __restrict__ w1s,
                     __half* __restrict__ w2s)
{
    const unsigned ub = blockIdx.x * 256u;           // first unit of this block
    const float* in; __half* out; unsigned base;
    if      (ub <  1048576u) { in = x;    out = xs;    base = 0u; }
    else if (ub <  1835008u) { in = w_in; out = wins;  base = 1048576u; }
    else if (ub <  2097152u) { in = wo;   out = wouts; base = 1835008u; }
    else if (ub <  3145728u) { in = w1;   out = w1s;   base = 2097152u; }
    else                     { in = w2;   out = w2s;   base = 3145728u; }
    const size_t off = (size_t)(ub - base + threadIdx.x) * 4;
    float4 v = *(const float4*)(in + off);
    *(__half2*)(out + off)     = __half2{__float2half_rn(v.x), __float2half_rn(v.y)};
    *(__half2*)(out + off + 2) = __half2{__float2half_rn(v.z), __float2half_rn(v.w)};
}

// ===========================================================================
// HMMA GEMM (R13 proven core): C = A x W^T (+bias), fp16 operands, fp32 accum.
// Tile 128x128, 128 threads (4 warps, 2x2), warp tile 64x64, 2 CTAs/SM.
// K-chunk 64 (128B swizzled rows), 3-stage cp.async pipeline.
// smem: 3 x 32K = 96K per CTA -> 192K/SM with 2 CTAs.
// OUT_MODE 0: fp32 C + bias.  OUT_MODE 1: gelu(C+bias) -> fp16.
// ===========================================================================
#define STAGE_B 32768
#define GEMM_SMEM (3 * STAGE_B)

__device__ __forceinline__ void load_ab(const __half* A, const __half* W,
                                        int K, uint32_t sb, int tid,
                                        int m0, int n0, int c, int s)
{
    const size_t rb = (size_t)2 * K;                 // row bytes (K halves)
    const char* Ab = (const char*)A + (size_t)m0 * rb + (size_t)c * 128;
    const char* Wb = (const char*)W + (size_t)n0 * rb + (size_t)c * 128;
    const uint32_t as = sb + s * STAGE_B;
    const uint32_t ws = as + 16384;
#pragma unroll
    for (int i = 0; i < 8; i++) {                    // A: 128 rows x 128B
        int id = tid + i * 128;
        int r = id >> 3, cb = (id & 7) * 16;
        uint32_t off = (uint32_t)(r * 128 + cb); off ^= (off >> 3) & 0x70;
        cp16(as + off, Ab + (size_t)r * rb + cb);
    }
#pragma unroll
    for (int i = 0; i < 8; i++) {                    // W: 128 rows x 128B
        int id = tid + i * 128;
        int r = id >> 3, cb = (id & 7) * 16;
        uint32_t off = (uint32_t)(r * 128 + cb); off ^= (off >> 3) & 0x70;
        cp16(ws + off, Wb + (size_t)r * rb + cb);
    }
    CP_COMMIT();
}

template <int OUT_MODE>
__global__ __launch_bounds__(128, 2)
void gemm_kernel(const __half* __restrict__ A, const __half* __restrict__ W,
                 const float* __restrict__ bias, float* __restrict__ outF,
                 __half* __restrict__ outS, int Ntot, int K)
{
    extern __shared__ char smem[];
    const uint32_t sb = smem_to_u32(smem);
    const int tid = threadIdx.x, wid = tid >> 5, lane = tid & 31;
    const int wm = wid >> 1, wn = wid & 1;           // 2 x 2 warps
    const int m0 = blockIdx.y * 128, n0 = blockIdx.x * 128;
    const int NC = K / 64;

    float acc[4][8][4];                              // warp tile 64x64
#pragma unroll
    for (int i = 0; i < 4; i++)
#pragma unroll
        for (int j = 0; j < 8; j++)
#pragma unroll
            for (int q = 0; q < 4; q++) acc[i][j][q] = 0.0f;

    // A ldsm4: lane q = lane>>3 -> (m-half, k-half)
    const int aq   = lane >> 3;
    const int ari  = lane & 7;
    const int arow = wm * 64 + (aq & 1) * 8 + ari;   // + ma*16
    const int akc  = aq >> 1;
    // B ldsm4: lanes 0-15 -> n-atom 2p (k0,k1), lanes 16-31 -> n-atom 2p+1
    const int bna2 = lane >> 4;
    const int bq   = (lane >> 3) & 1;
    const int bri  = lane & 7;
    const int brow = wn * 64 + bna2 * 8 + bri;       // + pair*16

    load_ab(A, W, K, sb, tid, m0, n0, 0, 0);
    load_ab(A, W, K, sb, tid, m0, n0, 1, 1);

    for (int c = 0; c < NC; c++) {
        if (c + 1 == NC) { CP_WAIT0(); } else { CP_WAIT1(); }
        __syncthreads();
        if (c + 2 < NC) load_ab(A, W, K, sb, tid, m0, n0, c + 2, (c + 2) % 3);

        const int s = c % 3;
        const uint32_t as = sb + s * STAGE_B;
        const uint32_t ws = as + 16384;
#pragma unroll
        for (int ks = 0; ks < 4; ks++) {
            const int kc = ks * 2;
            uint32_t bh[16];                          // frag na: {bh[2na], bh[2na+1]}
            const uint32_t bsw = ((uint32_t)((kc + bq) ^ bri)) << 4;
#pragma unroll
            for (int p = 0; p < 4; p++)
                ldsm4(&bh[4 * p], ws + (brow + p * 16) * 128 + bsw);
            const uint32_t asw = ((uint32_t)((kc + akc) ^ ari)) << 4;
#pragma unroll
            for (int ma = 0; ma < 4; ma++) {
                uint32_t ah[4];
                ldsm4(ah, as + (arow + ma * 16) * 128 + asw);
#pragma unroll
                for (int na = 0; na < 8; na++)
                    mma16816(acc[ma][na], ah, &bh[2 * na]);
            }
        }
    }

    // epilogue
    const int lrow = lane >> 2;
    const int lcol = (lane & 3) * 2;
#pragma unroll
    for (int ma = 0; ma < 4; ma++) {
        const int r0 = m0 + wm * 64 + ma * 16 + lrow;
#pragma unroll
        for (int na = 0; na < 8; na++) {
            const int c0 = n0 + wn * 64 + na * 8 + lcol;
            float v0 = acc[ma][na][0] + bias[c0];
            float v1 = acc[ma][na][1] + bias[c0 + 1];
            float v2 = acc[ma][na][2] + bias[c0];
            float v3 = acc[ma][na][3] + bias[c0 + 1];
            if (OUT_MODE == 0) {
                *(float2*)(outF + (size_t)r0 * Ntot + c0)     = make_float2(v0, v1);
                *(float2*)(outF + (size_t)(r0+8) * Ntot + c0) = make_float2(v2, v3);
            } else {
                v0 = gelu_exact(v0); v1 = gelu_exact(v1);
                v2 = gelu_exact(v2); v3 = gelu_exact(v3);
                *(__half2*)(outS + (size_t)r0 * Ntot + c0) =
                    __half2{__float2half_rn(v0), __float2half_rn(v1)};
                *(__half2*)(outS + (size_t)(r0+8) * Ntot + c0) =
                    __half2{__float2half_rn(v2), __float2half_rn(v3)};
            }
        }
    }
}

// ===========================================================================
// Local causal attention (fp32 in, fp16 out)
// ===========================================================================
__global__ __launch_bounds__(256)
void attn_kernel(const float* __restrict__ qkv, __half* __restrict__ attns)
{
    const int w    = (blockIdx.x * blockDim.x + threadIdx.x) >> 5;
    const int lane = threadIdx.x & 31;
    if (w >= MTOK * HEADS) return;
    const int m = w / HEADS, h = w - m * HEADS, s = m & (SEQ - 1);

    const float* qp = qkv + (size_t)m * (3 * DIMX) + h * HD;
    const float qa = qp[lane], qb = qp[lane + 32];
    const int jlo = (s >= WIN - 1) ? (s - (WIN - 1)) : 0;
    const int cnt = s - jlo + 1;
    const int mlo = m - (s - jlo);

    float sc[WIN];
#pragma unroll
    for (int t = 0; t < WIN; t++) {
        sc[t] = -3.0e38f;
        if (t < cnt) {
            const float* kp = qkv + (size_t)(mlo + t) * (3 * DIMX) + DIMX + h * HD;
            float d = qa * kp[lane] + qb * kp[lane + 32];
#pragma unroll
            for (int o = 16; o > 0; o >>= 1) d += __shfl_xor_sync(0xffffffffu, d, o);
            sc[t] = d * 0.125f;
        }
    }
    float mx = sc[0];
#pragma unroll
    for (int t = 1; t < WIN; t++) mx = fmaxf(mx, sc[t]);
    float p[WIN], sum = 0.0f;
#pragma unroll
    for (int t = 0; t < WIN; t++) { p[t] = (t < cnt) ? __expf(sc[t] - mx) : 0.0f; sum += p[t]; }
    const float inv = 1.0f / sum;

    float oa = 0.0f, ob = 0.0f;
#pragma unroll
    for (int t = 0; t < WIN; t++) {
        if (t < cnt) {
            const float* vp = qkv + (size_t)(mlo + t) * (3 * DIMX) + 2 * DIMX + h * HD;
            oa = fmaf(p[t], vp[lane], oa);
            ob = fmaf(p[t], vp[lane + 32], ob);
        }
    }
    const size_t base = (size_t)m * DIMX + h * HD;
    attns[base + lane]      = __float2half_rn(oa * inv);
    attns[base + lane + 32] = __float2half_rn(ob * inv);
}

// ===========================================================================
// Residual + LayerNorm, float4-vectorized (optionally emit fp16 cast)
// ===========================================================================
template <int CAST>
__global__ __launch_bounds__(256)
void ln_residual_kernel(const float* __restrict__ A, const float* __restrict__ Bv,
                        const float* __restrict__ g, const float* __restrict__ beta,
                        float* __restrict__ out, __half* __restrict__ outs)
{
    const int m = blockIdx.x, tid = threadIdx.x;
    const float4* a4 = (const float4*)(A  + (size_t)m * DIMX);
    const float4* b4 = (const float4*)(Bv + (size_t)m * DIMX);

    float4 av = a4[tid], bv = b4[tid];
    float4 v = make_float4(av.x + bv.x, av.y + bv.y, av.z + bv.z, av.w + bv.w);
    float s  = v.x + v.y + v.z + v.w;
    float s2 = v.x*v.x + v.y*v.y + v.z*v.z + v.w*v.w;
#pragma unroll
    for (int o = 16; o > 0; o >>= 1) {
        s  += __shfl_xor_sync(0xffffffffu, s,  o);
        s2 += __shfl_xor_sync(0xffffffffu, s2, o);
    }
    __shared__ float shs[8], shs2[8], shm, shr;
    const int wid = tid >> 5, lane = tid & 31;
    if (lane == 0) { shs[wid] = s; shs2[wid] = s2; }
    __syncthreads();
    if (tid == 0) {
        float S = 0.0f, S2 = 0.0f;
#pragma unroll
        for (int i = 0; i < 8; i++) { S += shs[i]; S2 += shs2[i]; }
        float mean = S * (1.0f / DIMX);
        shm = mean;
        shr = rsqrtf(S2 * (1.0f / DIMX) - mean * mean + EPSLN);
    }
    __syncthreads();
    const float mean = shm, rstd = shr;
    float4 gv = ((const float4*)g)[tid];
    float4 be = ((const float4*)beta)[tid];
    float4 y;
    y.x = (v.x - mean) * rstd * gv.x + be.x;
    y.y = (v.y - mean) * rstd * gv.y + be.y;
    y.z = (v.z - mean) * rstd * gv.z + be.z;
    y.w = (v.w - mean) * rstd * gv.w + be.w;
    ((float4*)(out + (size_t)m * DIMX))[tid] = y;
    if (CAST) {
        __half2* o2 = (__half2*)(outs + (size_t)m * DIMX + tid * 4);
        o2[0] = __half2{__float2half_rn(y.x), __float2half_rn(y.y)};
        o2[1] = __half2{__float2half_rn(y.z), __float2half_rn(y.w)};
    }
}

// ===========================================================================
// kernel_launch
// ===========================================================================
extern "C" void kernel_launch(void* const* d_in, const int* in_sizes, int n_in,
                              void* d_out, int out_size)
{
    const float* x     = (const float*)d_in[0];
    const float* w_in  = (const float*)d_in[1];
    const float* b_in  = (const float*)d_in[2];
    const float* w_out = (const float*)d_in[3];
    const float* b_out = (const float*)d_in[4];
    const float* ln1_g = (const float*)d_in[5];
    const float* ln1_b = (const float*)d_in[6];
    const float* ln2_g = (const float*)d_in[7];
    const float* ln2_b = (const float*)d_in[8];
    const float* w1    = (const float*)d_in[9];
    const float* b1    = (const float*)d_in[10];
    const float* w2    = (const float*)d_in[11];
    const float* b2    = (const float*)d_in[12];
    float* out = (float*)d_out;

    float *qkv, *attnout, *x1, *mlp;
    __half *xs, *attns, *x1s, *hs, *wins, *wouts, *w1s, *w2s;
    cudaGetSymbolAddress((void**)&qkv,     g_qkv);
    cudaGetSymbolAddress((void**)&attnout, g_attnout);
    cudaGetSymbolAddress((void**)&x1,      g_x1);
    cudaGetSymbolAddress((void**)&mlp,     g_mlp);
    cudaGetSymbolAddress((void**)&xs,      g_xs);
    cudaGetSymbolAddress((void**)&attns,   g_attns);
    cudaGetSymbolAddress((void**)&x1s,     g_x1s);
    cudaGetSymbolAddress((void**)&hs,      g_hs);
    cudaGetSymbolAddress((void**)&wins,    g_wins);
    cudaGetSymbolAddress((void**)&wouts,   g_wouts);
    cudaGetSymbolAddress((void**)&w1s,     g_w1s);
    cudaGetSymbolAddress((void**)&w2s,     g_w2s);

    cudaFuncSetAttribute(gemm_kernel<0>, cudaFuncAttributeMaxDynamicSharedMemorySize, GEMM_SMEM);
    cudaFuncSetAttribute(gemm_kernel<1>, cudaFuncAttributeMaxDynamicSharedMemorySize, GEMM_SMEM);

    // 0. all fp32 -> fp16 casts, branchless per-block-region
    cast_all_kernel<<<16384, 256>>>(x, w_in, w_out, w1, w2, xs, wins, wouts, w1s, w2s);

    // 1. qkv = x @ w_in^T + b_in           [4096, 3072], K=1024
    gemm_kernel<0><<<dim3(24, 32), 128, GEMM_SMEM>>>(xs, wins, b_in, qkv, nullptr, 3072, 1024);
    // 2. attention -> fp16
    attn_kernel<<<(MTOK * HEADS * 32) / 256, 256>>>(qkv, attns);
    // 3. attnout = attn @ w_out^T + b_out  [4096, 1024], K=1024
    gemm_kernel<0><<<dim3(8, 32), 128, GEMM_SMEM>>>(attns, wouts, b_out, attnout, nullptr, 1024, 1024);
    // 4. x1 = LN1(x + attnout), + fp16 cast
    ln_residual_kernel<1><<<MTOK, 256>>>(x, attnout, ln1_g, ln1_b, x1, x1s);
    // 5. h = gelu(x1 @ w1^T + b1) -> fp16  [4096, 4096], K=1024
    gemm_kernel<1><<<dim3(32, 32), 128, GEMM_SMEM>>>(x1s, w1s, b1, nullptr, hs, 4096, 1024);
    // 6. mlp = h @ w2^T + b2               [4096, 1024], K=4096
    gemm_kernel<0><<<dim3(8, 32), 128, GEMM_SMEM>>>(hs, w2s, b2, mlp, nullptr, 1024, 4096);
    // 7. out = LN2(x1 + mlp)
    ln_residual_kernel<0><<<MTOK, 256>>>(x1, mlp, ln2_g, ln2_b, out, nullptr);

    (void)in_sizes; (void)n_in; (void)out_size;
}